// round 7
// baseline (speedup 1.0000x reference)
#include <cuda_runtime.h>
#include <math.h>
#include <stdint.h>

// Problem constants
#define BSZ   2
#define TSEQ  2048
#define NH    16
#define HD    64
#define CDIM  1024
#define N3    (3 * CDIM)
#define MROWS (BSZ * TSEQ)          // 4096

// Scratch (device globals: allocation-free per harness rules)
__device__ float g_q[(size_t)BSZ * NH * TSEQ * HD];
__device__ float g_k[(size_t)BSZ * NH * TSEQ * HD];
__device__ float g_v[(size_t)BSZ * NH * TSEQ * HD];
__device__ float g_y[(size_t)BSZ * TSEQ * CDIM];
__device__ float g_x[(size_t)MROWS * CDIM];        // tf32-rounded x
__device__ float g_wattn[(size_t)CDIM * N3];       // tf32-rounded W_attn
__device__ float g_wproj[(size_t)CDIM * CDIM];     // tf32-rounded W_proj

// ---------------------------------------------------------------------------
// helpers
// ---------------------------------------------------------------------------
__device__ __forceinline__ uint32_t f2tf32(float x) {
    uint32_t u;
    asm("cvt.rn.tf32.f32 %0, %1;" : "=r"(u) : "f"(x));
    return u;
}
__device__ __forceinline__ float rnd_tf32(float x) {
    return __uint_as_float(f2tf32(x));
}
__device__ __forceinline__ uint32_t smem_u32(const void* p) {
    uint32_t a;
    asm("{ .reg .u64 t; cvta.to.shared.u64 t, %1; cvt.u32.u64 %0, t; }"
        : "=r"(a) : "l"(p));
    return a;
}
__device__ __forceinline__ void cpa16(uint32_t dst, const void* src) {
    asm volatile("cp.async.cg.shared.global [%0], [%1], 16;"
                 :: "r"(dst), "l"(src));
}
#define CPA_COMMIT() asm volatile("cp.async.commit_group;" ::: "memory")
#define CPA_WAIT1()  asm volatile("cp.async.wait_group 1;" ::: "memory")
#define CPA_WAIT0()  asm volatile("cp.async.wait_group 0;" ::: "memory")

__device__ __forceinline__ void mma_tf32(float* d, const uint32_t* a, const uint32_t* b) {
    asm volatile(
        "mma.sync.aligned.m16n8k8.row.col.f32.tf32.tf32.f32 "
        "{%0,%1,%2,%3}, {%4,%5,%6,%7}, {%8,%9}, {%0,%1,%2,%3};"
        : "+f"(d[0]), "+f"(d[1]), "+f"(d[2]), "+f"(d[3])
        : "r"(a[0]), "r"(a[1]), "r"(a[2]), "r"(a[3]), "r"(b[0]), "r"(b[1]));
}

// ---------------------------------------------------------------------------
// Prep: round arrays to tf32 (RN) once per launch. DST: 0=g_x 1=g_wattn 2=g_wproj
// ---------------------------------------------------------------------------
template <int DST>
__global__ __launch_bounds__(256) void round_tf32_kernel(const float* __restrict__ src, int n4)
{
    float* dst = (DST == 0) ? g_x : (DST == 1) ? g_wattn : g_wproj;
    const int i = blockIdx.x * blockDim.x + threadIdx.x;
    if (i < n4) {
        float4 v = ((const float4*)src)[i];
        v.x = rnd_tf32(v.x); v.y = rnd_tf32(v.y);
        v.z = rnd_tf32(v.z); v.w = rnd_tf32(v.w);
        ((float4*)dst)[i] = v;
    }
}

// ---------------------------------------------------------------------------
// tf32 mma.sync GEMM, 3-stage cp.async pipeline.
// CTA 128x256, warp 64x64, BK=32. Operands pre-rounded tf32 (raw smem reads).
// A smem [128][36], B smem [32][264] — conflict-free fragment LDS.
// MODE 0: A=g_x, W=g_wattn, epilogue scatter->q/k/v (tf32-rounded)
// MODE 1: A=g_y, W=g_wproj, epilogue -> out (f32)
// ---------------------------------------------------------------------------
#define BM 128
#define BN 256
#define BK 32
#define NCHUNK  (CDIM / BK)            // 32
#define APITCH  36
#define BPITCH  264
#define A_FL    (BM * APITCH)          // 4608
#define B_FL    (BK * BPITCH)          // 8448
#define ST_FL   (A_FL + B_FL)          // 13056
#define GEMM_DYN (3 * ST_FL * 4)       // 156672 bytes

template <int MODE>
__global__ __launch_bounds__(256)
void tc_gemm_kernel(const float* __restrict__ bias, float* __restrict__ out)
{
    extern __shared__ __align__(16) float sm[];
    __shared__ float sbias[BN];
    const uint32_t sb = smem_u32(sm);
    const uint32_t* smu = (const uint32_t*)sm;

    const float* __restrict__ A = (MODE == 0) ? g_x : g_y;
    const float* __restrict__ W = (MODE == 0) ? g_wattn : g_wproj;
    const int ldb = (MODE == 0) ? N3 : CDIM;

    const int tid    = threadIdx.x;
    const int lane   = tid & 31;
    const int wid    = tid >> 5;
    const int warp_m = wid & 1;
    const int warp_n = wid >> 1;
    const int m0 = blockIdx.y * BM;
    const int n0 = blockIdx.x * BN;

    sbias[tid] = bias[n0 + tid];

    float acc[4][8][4];
#pragma unroll
    for (int mf = 0; mf < 4; mf++)
#pragma unroll
        for (int nf = 0; nf < 8; nf++)
#pragma unroll
            for (int r = 0; r < 4; r++) acc[mf][nf][r] = 0.f;

    // stage fill via cp.async (16B granules)
#define GEMM_FILL(slot, k0) do {                                                \
    const uint32_t ab = sb + (uint32_t)(slot) * (ST_FL * 4);                    \
    const uint32_t bb = ab + A_FL * 4;                                          \
    _Pragma("unroll")                                                           \
    for (int u = 0; u < 4; u++) {                                               \
        const int idx = tid + u * 256;                                          \
        const int row = idx >> 3, c4 = idx & 7;                                 \
        cpa16(ab + (uint32_t)(row * APITCH + c4 * 4) * 4,                       \
              A + (size_t)(m0 + row) * CDIM + (k0) + c4 * 4);                   \
    }                                                                           \
    _Pragma("unroll")                                                           \
    for (int u = 0; u < 8; u++) {                                               \
        const int idx = tid + u * 256;                                          \
        const int k = idx >> 6, n4 = idx & 63;                                  \
        cpa16(bb + (uint32_t)(k * BPITCH + n4 * 4) * 4,                         \
              W + (size_t)((k0) + k) * ldb + n0 + n4 * 4);                      \
    }                                                                           \
} while (0)

    GEMM_FILL(0, 0);  CPA_COMMIT();
    GEMM_FILL(1, BK); CPA_COMMIT();

    for (int i = 0; i < NCHUNK; i++) {
        if (i < NCHUNK - 1) CPA_WAIT1(); else CPA_WAIT0();
        __syncthreads();
        if (i + 2 < NCHUNK) {
            GEMM_FILL((i + 2) % 3, (i + 2) * BK);
            CPA_COMMIT();
        }
        // compute on stage i%3
        const uint32_t* As = smu + (i % 3) * ST_FL;
        const uint32_t* Bs = As + A_FL;
#pragma unroll
        for (int kk = 0; kk < BK; kk += 8) {
            uint32_t a[4][4], b[8][2];
            const int ka = kk + (lane & 3);
#pragma unroll
            for (int mf = 0; mf < 4; mf++) {
                const int m = warp_m * 64 + mf * 16 + (lane >> 2);
                a[mf][0] = As[m * APITCH + ka];
                a[mf][1] = As[(m + 8) * APITCH + ka];
                a[mf][2] = As[m * APITCH + ka + 4];
                a[mf][3] = As[(m + 8) * APITCH + ka + 4];
            }
#pragma unroll
            for (int nf = 0; nf < 8; nf++) {
                const int n = warp_n * 64 + nf * 8 + (lane >> 2);
                b[nf][0] = Bs[ka * BPITCH + n];
                b[nf][1] = Bs[(ka + 4) * BPITCH + n];
            }
#pragma unroll
            for (int mf = 0; mf < 4; mf++)
#pragma unroll
                for (int nf = 0; nf < 8; nf++)
                    mma_tf32(acc[mf][nf], a[mf], b[nf]);
        }
    }
#undef GEMM_FILL

    // ---- epilogue ----
#pragma unroll
    for (int mf = 0; mf < 4; mf++) {
        const int r0 = m0 + warp_m * 64 + mf * 16 + (lane >> 2);
#pragma unroll
        for (int nf = 0; nf < 8; nf++) {
            const int cb_loc = warp_n * 64 + nf * 8 + 2 * (lane & 3);
            const float b0 = sbias[cb_loc], b1 = sbias[cb_loc + 1];
            if (MODE == 0) {
                // tf32-round q/k/v at store (operand prep for attention)
                float2 v0 = make_float2(rnd_tf32(acc[mf][nf][0] + b0),
                                        rnd_tf32(acc[mf][nf][1] + b1));
                float2 v1 = make_float2(rnd_tf32(acc[mf][nf][2] + b0),
                                        rnd_tf32(acc[mf][nf][3] + b1));
                const int col = n0 + cb_loc;
                const int sec = col >> 10;
                const int c   = col & (CDIM - 1);
                const int h   = c >> 6;
                const int d0  = c & (HD - 1);
                float* dst = (sec == 0) ? g_q : ((sec == 1) ? g_k : g_v);
                const int bb0 = r0 >> 11, t0 = r0 & (TSEQ - 1);
                *(float2*)(dst + (((size_t)bb0 * NH + h) * TSEQ + t0) * HD + d0) = v0;
                const int r1 = r0 + 8;
                const int bb1 = r1 >> 11, t1 = r1 & (TSEQ - 1);
                *(float2*)(dst + (((size_t)bb1 * NH + h) * TSEQ + t1) * HD + d0) = v1;
            } else {
                float2 v0 = make_float2(acc[mf][nf][0] + b0, acc[mf][nf][1] + b1);
                float2 v1 = make_float2(acc[mf][nf][2] + b0, acc[mf][nf][3] + b1);
                *(float2*)(out + (size_t)r0 * CDIM + n0 + cb_loc) = v0;
                *(float2*)(out + (size_t)(r0 + 8) * CDIM + n0 + cb_loc) = v1;
            }
        }
    }
}

// ---------------------------------------------------------------------------
// Causal flash attention, tf32 mma.sync.
// CTA: 128 q-rows, 128 threads (4 warps x 32 rows), K-tile 64 keys,
// 2-stage cp.async KV (operands pre-rounded tf32), 2 CTAs/SM.
// Q/P [128][68], K [2][64][68], V [2][64][72].
// ---------------------------------------------------------------------------
#define AQPIT 68
#define AKPIT 68
#define AVPIT 72
#define ATT_Q_FL (128 * AQPIT)              // 8704
#define ATT_K_FL (64 * AKPIT)               // 4352
#define ATT_V_FL (64 * AVPIT)               // 4608
#define ATT_SMEM ((ATT_Q_FL + 2 * ATT_K_FL + 2 * ATT_V_FL) * 4)   // 106496 B

__global__ __launch_bounds__(128, 2) void attn_tc_kernel()
{
    extern __shared__ __align__(16) float smf[];
    uint32_t* smu = (uint32_t*)smf;
    const uint32_t sb = smem_u32(smf);

    const int tid  = threadIdx.x;
    const int lane = tid & 31;
    const int w    = tid >> 5;                    // 0..3
    const int qi   = (int)(gridDim.x - 1 - blockIdx.x);   // LPT: big tiles first
    const int bh   = blockIdx.y;

    const size_t hoff = (size_t)bh * TSEQ * HD;
    const float* Qg = g_q + hoff + (size_t)qi * 128 * HD;
    const float* Kg = g_k + hoff;
    const float* Vg = g_v + hoff;

    const int nkt = 2 * qi + 2;

#define ATT_FILLKV(slot, kt) do {                                               \
    const float* kp = Kg + (size_t)(kt) * 64 * HD;                              \
    const float* vp = Vg + (size_t)(kt) * 64 * HD;                              \
    const uint32_t kb = sb + (uint32_t)(ATT_Q_FL + (slot) * ATT_K_FL) * 4;      \
    const uint32_t vb = sb + (uint32_t)(ATT_Q_FL + 2 * ATT_K_FL + (slot) * ATT_V_FL) * 4; \
    _Pragma("unroll")                                                           \
    for (int u = 0; u < 8; u++) {                                               \
        const int idx = tid + u * 128;                                          \
        const int r = idx >> 4, c4 = idx & 15;                                  \
        cpa16(kb + (uint32_t)(r * AKPIT + c4 * 4) * 4, kp + (size_t)r * HD + c4 * 4); \
        cpa16(vb + (uint32_t)(r * AVPIT + c4 * 4) * 4, vp + (size_t)r * HD + c4 * 4); \
    }                                                                           \
} while (0)

    // ---- prologue: Q + KV stage 0 (group 0), KV stage 1 (group 1) ----
#pragma unroll
    for (int u = 0; u < 16; u++) {
        const int idx = tid + u * 128;
        const int r = idx >> 4, c4 = idx & 15;
        cpa16(sb + (uint32_t)(r * AQPIT + c4 * 4) * 4, Qg + (size_t)r * HD + c4 * 4);
    }
    ATT_FILLKV(0, 0);
    CPA_COMMIT();
    if (nkt > 1) { ATT_FILLKV(1, 1); CPA_COMMIT(); CPA_WAIT1(); }
    else         { CPA_WAIT0(); }
    __syncthreads();

    // ---- extract Q fragments (scaled by 1/8; exact on tf32 values) ----
    uint32_t qf[2][8][4];
#pragma unroll
    for (int mf = 0; mf < 2; mf++) {
        const int rb = w * 32 + mf * 16 + (lane >> 2);
#pragma unroll
        for (int kf = 0; kf < 8; kf++) {
            const int ka = kf * 8 + (lane & 3);
            qf[mf][kf][0] = __float_as_uint(smf[rb * AQPIT + ka] * 0.125f);
            qf[mf][kf][1] = __float_as_uint(smf[(rb + 8) * AQPIT + ka] * 0.125f);
            qf[mf][kf][2] = __float_as_uint(smf[rb * AQPIT + ka + 4] * 0.125f);
            qf[mf][kf][3] = __float_as_uint(smf[(rb + 8) * AQPIT + ka + 4] * 0.125f);
        }
    }
    __syncwarp();

    float o[2][8][4];
#pragma unroll
    for (int mf = 0; mf < 2; mf++)
#pragma unroll
        for (int nf = 0; nf < 8; nf++)
#pragma unroll
            for (int e = 0; e < 4; e++) o[mf][nf][e] = 0.f;
    float mrow[2][2] = {{-INFINITY, -INFINITY}, {-INFINITY, -INFINITY}};
    float lrow[2][2] = {{0.f, 0.f}, {0.f, 0.f}};

    for (int kt = 0; kt < nkt; kt++) {
        if (kt < nkt - 1) CPA_WAIT1(); else CPA_WAIT0();
        __syncthreads();
        const uint32_t* Ks = smu + ATT_Q_FL + (kt & 1) * ATT_K_FL;
        const uint32_t* Vs = smu + ATT_Q_FL + 2 * ATT_K_FL + (kt & 1) * ATT_V_FL;

        // ---- S = (Q/8) @ K^T ----
        float s[2][8][4];
#pragma unroll
        for (int mf = 0; mf < 2; mf++)
#pragma unroll
            for (int nf = 0; nf < 8; nf++)
#pragma unroll
                for (int e = 0; e < 4; e++) s[mf][nf][e] = 0.f;

#pragma unroll
        for (int kf = 0; kf < 8; kf++) {
            const int ka = kf * 8 + (lane & 3);
#pragma unroll
            for (int nf = 0; nf < 8; nf++) {
                const int n = nf * 8 + (lane >> 2);
                uint32_t bb[2] = {Ks[n * AKPIT + ka], Ks[n * AKPIT + ka + 4]};
                mma_tf32(s[0][nf], qf[0][kf], bb);
                mma_tf32(s[1][nf], qf[1][kf], bb);
            }
        }

        // ---- causal mask (only the two diagonal tiles) ----
        if (kt >= nkt - 2) {
#pragma unroll
            for (int mf = 0; mf < 2; mf++) {
                const int rb = qi * 128 + w * 32 + mf * 16 + (lane >> 2);
#pragma unroll
                for (int nf = 0; nf < 8; nf++) {
                    const int cg = kt * 64 + nf * 8 + 2 * (lane & 3);
                    if (cg     > rb)     s[mf][nf][0] = -INFINITY;
                    if (cg + 1 > rb)     s[mf][nf][1] = -INFINITY;
                    if (cg     > rb + 8) s[mf][nf][2] = -INFINITY;
                    if (cg + 1 > rb + 8) s[mf][nf][3] = -INFINITY;
                }
            }
        }

        // ---- online softmax + P store (warp-private smem rows) ----
#pragma unroll
        for (int mf = 0; mf < 2; mf++) {
            float rm0 = -INFINITY, rm1 = -INFINITY;
#pragma unroll
            for (int nf = 0; nf < 8; nf++) {
                rm0 = fmaxf(rm0, fmaxf(s[mf][nf][0], s[mf][nf][1]));
                rm1 = fmaxf(rm1, fmaxf(s[mf][nf][2], s[mf][nf][3]));
            }
            rm0 = fmaxf(rm0, __shfl_xor_sync(0xFFFFFFFF, rm0, 1));
            rm0 = fmaxf(rm0, __shfl_xor_sync(0xFFFFFFFF, rm0, 2));
            rm1 = fmaxf(rm1, __shfl_xor_sync(0xFFFFFFFF, rm1, 1));
            rm1 = fmaxf(rm1, __shfl_xor_sync(0xFFFFFFFF, rm1, 2));
            const float mn0 = fmaxf(mrow[mf][0], rm0);
            const float mn1 = fmaxf(mrow[mf][1], rm1);
            const float c0 = __expf(mrow[mf][0] - mn0);
            const float c1 = __expf(mrow[mf][1] - mn1);
            mrow[mf][0] = mn0; mrow[mf][1] = mn1;
            float rs0 = 0.f, rs1 = 0.f;
            const int rb_l = w * 32 + mf * 16 + (lane >> 2);
#pragma unroll
            for (int nf = 0; nf < 8; nf++) {
                const float p0 = __expf(s[mf][nf][0] - mn0);
                const float p1 = __expf(s[mf][nf][1] - mn0);
                const float p2 = __expf(s[mf][nf][2] - mn1);
                const float p3 = __expf(s[mf][nf][3] - mn1);
                rs0 += p0 + p1; rs1 += p2 + p3;
                o[mf][nf][0] *= c0; o[mf][nf][1] *= c0;
                o[mf][nf][2] *= c1; o[mf][nf][3] *= c1;
                const int cb = nf * 8 + 2 * (lane & 3);
                smu[rb_l * AQPIT + cb]       = f2tf32(p0);
                smu[rb_l * AQPIT + cb + 1]   = f2tf32(p1);
                smu[(rb_l + 8) * AQPIT + cb]     = f2tf32(p2);
                smu[(rb_l + 8) * AQPIT + cb + 1] = f2tf32(p3);
            }
            rs0 += __shfl_xor_sync(0xFFFFFFFF, rs0, 1);
            rs0 += __shfl_xor_sync(0xFFFFFFFF, rs0, 2);
            rs1 += __shfl_xor_sync(0xFFFFFFFF, rs1, 1);
            rs1 += __shfl_xor_sync(0xFFFFFFFF, rs1, 2);
            lrow[mf][0] = lrow[mf][0] * c0 + rs0;
            lrow[mf][1] = lrow[mf][1] * c1 + rs1;
        }
        __syncwarp();

        // ---- O += P @ V ----
#pragma unroll
        for (int kf = 0; kf < 8; kf++) {
            const int ka = kf * 8 + (lane & 3);
            const int r0 = w * 32 + (lane >> 2);
            uint32_t a0[4], a1[4];
            a0[0] = smu[r0 * AQPIT + ka];
            a0[1] = smu[(r0 + 8) * AQPIT + ka];
            a0[2] = smu[r0 * AQPIT + ka + 4];
            a0[3] = smu[(r0 + 8) * AQPIT + ka + 4];
            a1[0] = smu[(r0 + 16) * AQPIT + ka];
            a1[1] = smu[(r0 + 24) * AQPIT + ka];
            a1[2] = smu[(r0 + 16) * AQPIT + ka + 4];
            a1[3] = smu[(r0 + 24) * AQPIT + ka + 4];
#pragma unroll
            for (int nf = 0; nf < 8; nf++) {
                const int d = nf * 8 + (lane >> 2);
                uint32_t vb[2] = {Vs[(kf * 8 + (lane & 3)) * AVPIT + d],
                                  Vs[(kf * 8 + (lane & 3) + 4) * AVPIT + d]};
                mma_tf32(o[0][nf], a0, vb);
                mma_tf32(o[1][nf], a1, vb);
            }
        }
        __syncthreads();
        if (kt + 2 < nkt) {
            ATT_FILLKV((kt + 2) & 1, kt + 2);
            CPA_COMMIT();
        }
    }
#undef ATT_FILLKV

    // ---- normalize + write g_y (tf32-rounded: proj operand) ----
    const int b = bh >> 4;
    const int h = bh & 15;
#pragma unroll
    for (int mf = 0; mf < 2; mf++) {
        const float inv0 = 1.0f / lrow[mf][0];
        const float inv1 = 1.0f / lrow[mf][1];
        const int t0 = qi * 128 + w * 32 + mf * 16 + (lane >> 2);
        float* yrow0 = g_y + ((size_t)b * TSEQ + t0) * CDIM + h * 64;
        float* yrow1 = g_y + ((size_t)b * TSEQ + t0 + 8) * CDIM + h * 64;
#pragma unroll
        for (int nf = 0; nf < 8; nf++) {
            const int c = nf * 8 + 2 * (lane & 3);
            *(float2*)(yrow0 + c) = make_float2(rnd_tf32(o[mf][nf][0] * inv0),
                                                rnd_tf32(o[mf][nf][1] * inv0));
            *(float2*)(yrow1 + c) = make_float2(rnd_tf32(o[mf][nf][2] * inv1),
                                                rnd_tf32(o[mf][nf][3] * inv1));
        }
    }
}

// ---------------------------------------------------------------------------
extern "C" void kernel_launch(void* const* d_in, const int* in_sizes, int n_in,
                              void* d_out, int out_size)
{
    const float* x      = (const float*)d_in[0];
    const float* W_attn = (const float*)d_in[1];
    const float* b_attn = (const float*)d_in[2];
    const float* W_proj = (const float*)d_in[3];
    const float* b_proj = (const float*)d_in[4];
    float* out = (float*)d_out;

    static bool attr_set = false;
    if (!attr_set) {
        cudaFuncSetAttribute(attn_tc_kernel,
                             cudaFuncAttributeMaxDynamicSharedMemorySize, ATT_SMEM);
        cudaFuncSetAttribute((const void*)tc_gemm_kernel<0>,
                             cudaFuncAttributeMaxDynamicSharedMemorySize, GEMM_DYN);
        cudaFuncSetAttribute((const void*)tc_gemm_kernel<1>,
                             cudaFuncAttributeMaxDynamicSharedMemorySize, GEMM_DYN);
        attr_set = true;
    }

    // 0) pre-round operands to tf32
    round_tf32_kernel<0><<<(MROWS * CDIM / 4 + 255) / 256, 256>>>(x, MROWS * CDIM / 4);
    round_tf32_kernel<1><<<(CDIM * N3 / 4 + 255) / 256, 256>>>(W_attn, CDIM * N3 / 4);
    round_tf32_kernel<2><<<(CDIM * CDIM / 4 + 255) / 256, 256>>>(W_proj, CDIM * CDIM / 4);

    // 1) QKV GEMM
    {
        dim3 grid(N3 / BN, MROWS / BM);
        tc_gemm_kernel<0><<<grid, 256, GEMM_DYN>>>(b_attn, nullptr);
    }
    // 2) Flash attention
    {
        dim3 grid(TSEQ / 128, BSZ * NH);
        attn_tc_kernel<<<grid, 128, ATT_SMEM>>>();
    }
    // 3) Projection GEMM
    {
        dim3 grid(CDIM / BN, MROWS / BM);
        tc_gemm_kernel<1><<<grid, 256, GEMM_DYN>>>(b_proj, out);
    }
}

// round 8
// speedup vs baseline: 1.8792x; 1.8792x over previous
#include <cuda_runtime.h>
#include <cuda_fp16.h>
#include <math.h>
#include <stdint.h>

// Problem constants
#define BSZ   2
#define TSEQ  2048
#define NH    16
#define HD    64
#define CDIM  1024
#define N3    (3 * CDIM)
#define MROWS (BSZ * TSEQ)          // 4096

// Scratch (device globals; all fp16 operands)
__device__ __half g_q[(size_t)BSZ * NH * TSEQ * HD];
__device__ __half g_k[(size_t)BSZ * NH * TSEQ * HD];
__device__ __half g_v[(size_t)BSZ * NH * TSEQ * HD];
__device__ __half g_y[(size_t)MROWS * CDIM];
__device__ __half g_x[(size_t)MROWS * CDIM];
__device__ __half g_wattn[(size_t)CDIM * N3];
__device__ __half g_wproj[(size_t)CDIM * CDIM];

// ---------------------------------------------------------------------------
// helpers
// ---------------------------------------------------------------------------
__device__ __forceinline__ uint32_t smem_u32(const void* p) {
    uint32_t a;
    asm("{ .reg .u64 t; cvta.to.shared.u64 t, %1; cvt.u32.u64 %0, t; }"
        : "=r"(a) : "l"(p));
    return a;
}
__device__ __forceinline__ void cpa16(uint32_t dst, const void* src) {
    asm volatile("cp.async.cg.shared.global [%0], [%1], 16;"
                 :: "r"(dst), "l"(src));
}
#define CPA_COMMIT() asm volatile("cp.async.commit_group;" ::: "memory")
template <int N>
__device__ __forceinline__ void cpa_wait() {
    asm volatile("cp.async.wait_group %0;" :: "n"(N) : "memory");
}
__device__ __forceinline__ void ldsm_x4(uint32_t* r, uint32_t addr) {
    asm volatile("ldmatrix.sync.aligned.m8n8.x4.shared.b16 {%0,%1,%2,%3}, [%4];"
                 : "=r"(r[0]), "=r"(r[1]), "=r"(r[2]), "=r"(r[3]) : "r"(addr));
}
__device__ __forceinline__ void ldsm_x4t(uint32_t* r, uint32_t addr) {
    asm volatile("ldmatrix.sync.aligned.m8n8.x4.trans.shared.b16 {%0,%1,%2,%3}, [%4];"
                 : "=r"(r[0]), "=r"(r[1]), "=r"(r[2]), "=r"(r[3]) : "r"(addr));
}
__device__ __forceinline__ void mma_f16(float* d, const uint32_t* a, const uint32_t* b) {
    asm volatile(
        "mma.sync.aligned.m16n8k16.row.col.f32.f16.f16.f32 "
        "{%0,%1,%2,%3}, {%4,%5,%6,%7}, {%8,%9}, {%0,%1,%2,%3};"
        : "+f"(d[0]), "+f"(d[1]), "+f"(d[2]), "+f"(d[3])
        : "r"(a[0]), "r"(a[1]), "r"(a[2]), "r"(a[3]), "r"(b[0]), "r"(b[1]));
}
__device__ __forceinline__ uint32_t pack_h2(float a, float b) {
    __half2 h = __floats2half2_rn(a, b);
    return *reinterpret_cast<uint32_t*>(&h);
}

// ---------------------------------------------------------------------------
// Prep: convert fp32 inputs to fp16. DST: 0=g_x 1=g_wattn 2=g_wproj
// ---------------------------------------------------------------------------
template <int DST>
__global__ __launch_bounds__(256) void to_half_kernel(const float* __restrict__ src, int n8)
{
    __half* dst = (DST == 0) ? g_x : (DST == 1) ? g_wattn : g_wproj;
    const int i = blockIdx.x * blockDim.x + threadIdx.x;
    if (i < n8) {
        float4 a = ((const float4*)src)[2 * i];
        float4 b = ((const float4*)src)[2 * i + 1];
        uint4 p;
        p.x = pack_h2(a.x, a.y); p.y = pack_h2(a.z, a.w);
        p.z = pack_h2(b.x, b.y); p.w = pack_h2(b.z, b.w);
        ((uint4*)dst)[i] = p;
    }
}

// ---------------------------------------------------------------------------
// fp16 mma.sync GEMM, 4-stage cp.async pipeline, ldmatrix fragments.
// CTA 128x256, warp 64x64, BK=32.
// A smem [128][40]h (5 granules/row), B smem [32][264]h (33 granules/row).
// MODE 0: A=g_x, W=g_wattn -> scatter q(*0.125)/k/v (half)
// MODE 1: A=g_y, W=g_wproj -> out (fp32)
// ---------------------------------------------------------------------------
#define BM 128
#define BN 256
#define BK 32
#define NCHUNK  (CDIM / BK)            // 32
#define APH 40
#define BPH 264
#define A_BY (BM * APH * 2)            // 10240
#define B_BY (BK * BPH * 2)            // 16896
#define ST_BY (A_BY + B_BY)            // 27136
#define GEMM_DYN (4 * ST_BY)           // 108544

template <int MODE>
__global__ __launch_bounds__(256)
void tc_gemm_kernel(const float* __restrict__ bias, float* __restrict__ out)
{
    extern __shared__ __align__(16) char smc[];
    __shared__ float sbias[BN];
    const uint32_t sb = smem_u32(smc);

    const __half* __restrict__ A = (MODE == 0) ? g_x : g_y;
    const __half* __restrict__ W = (MODE == 0) ? g_wattn : g_wproj;
    const int ldb = (MODE == 0) ? N3 : CDIM;

    const int tid    = threadIdx.x;
    const int lane   = tid & 31;
    const int wid    = tid >> 5;
    const int warp_m = wid & 1;
    const int warp_n = wid >> 1;
    const int m0 = blockIdx.y * BM;
    const int n0 = blockIdx.x * BN;

    sbias[tid] = bias[n0 + tid];

    float acc[4][8][4];
#pragma unroll
    for (int mf = 0; mf < 4; mf++)
#pragma unroll
        for (int nf = 0; nf < 8; nf++)
#pragma unroll
            for (int r = 0; r < 4; r++) acc[mf][nf][r] = 0.f;

#define GF(slot, k0) do {                                                       \
    const uint32_t ab_ = sb + (uint32_t)(slot) * ST_BY;                         \
    const uint32_t bb_ = ab_ + A_BY;                                            \
    _Pragma("unroll")                                                           \
    for (int u = 0; u < 2; u++) {                                               \
        const int idx = tid + u * 256;                                          \
        const int row = idx >> 2, g = idx & 3;                                  \
        cpa16(ab_ + (uint32_t)(row * APH + g * 8) * 2,                          \
              A + (size_t)(m0 + row) * CDIM + (k0) + g * 8);                    \
    }                                                                           \
    _Pragma("unroll")                                                           \
    for (int u = 0; u < 4; u++) {                                               \
        const int idx = tid + u * 256;                                          \
        const int row = idx >> 5, g = idx & 31;                                 \
        cpa16(bb_ + (uint32_t)(row * BPH + g * 8) * 2,                          \
              W + (size_t)((k0) + row) * ldb + n0 + g * 8);                     \
    }                                                                           \
} while (0)

    GF(0, 0);      CPA_COMMIT();
    GF(1, BK);     CPA_COMMIT();
    GF(2, 2 * BK); CPA_COMMIT();

    // ldmatrix lane address components
    const int r8 = lane & 7, q4 = lane >> 3;
    // A (x4, row-major): quad -> row base + (q&1)*8 + r8, col kk + (q>>1)*8
    const uint32_t a_base = (uint32_t)((warp_m * 64 + r8 + (q4 & 1) * 8) * APH
                                       + (q4 >> 1) * 8) * 2;
    // B (x4.trans on [k][n]): quad -> row kk + (q&1)*8 + r8, col n + (q>>1)*8
    const uint32_t b_base = (uint32_t)(((q4 & 1) * 8 + r8) * BPH
                                       + warp_n * 64 + (q4 >> 1) * 8) * 2;

    for (int i = 0; i < NCHUNK; i++) {
        cpa_wait<2>();
        __syncthreads();
        if (i + 3 < NCHUNK) GF((i + 3) & 3, (i + 3) * BK);
        CPA_COMMIT();

        const uint32_t ab = sb + (uint32_t)(i & 3) * ST_BY;
        const uint32_t bb = ab + A_BY;
#pragma unroll
        for (int kk = 0; kk < BK; kk += 16) {
            uint32_t a[4][4], b[4][4];
#pragma unroll
            for (int mf = 0; mf < 4; mf++)
                ldsm_x4(a[mf], ab + a_base + (uint32_t)(mf * 16 * APH + kk) * 2);
#pragma unroll
            for (int np = 0; np < 4; np++)
                ldsm_x4t(b[np], bb + b_base + (uint32_t)(kk * BPH + np * 16) * 2);
#pragma unroll
            for (int mf = 0; mf < 4; mf++)
#pragma unroll
                for (int nf = 0; nf < 8; nf++)
                    mma_f16(acc[mf][nf], a[mf], &b[nf >> 1][(nf & 1) * 2]);
        }
    }
#undef GF

    // ---- epilogue ----
#pragma unroll
    for (int mf = 0; mf < 4; mf++) {
        const int r0 = m0 + warp_m * 64 + mf * 16 + (lane >> 2);
#pragma unroll
        for (int nf = 0; nf < 8; nf++) {
            const int cb_loc = warp_n * 64 + nf * 8 + 2 * (lane & 3);
            const float b0 = sbias[cb_loc], b1 = sbias[cb_loc + 1];
            float e0 = acc[mf][nf][0] + b0, e1 = acc[mf][nf][1] + b1;
            float e2 = acc[mf][nf][2] + b0, e3 = acc[mf][nf][3] + b1;
            if (MODE == 0) {
                const int col = n0 + cb_loc;
                const int sec = col >> 10;
                if (sec == 0) { e0 *= 0.125f; e1 *= 0.125f; e2 *= 0.125f; e3 *= 0.125f; }
                const int c   = col & (CDIM - 1);
                const int h   = c >> 6;
                const int d0  = c & (HD - 1);
                __half* dst = (sec == 0) ? g_q : ((sec == 1) ? g_k : g_v);
                const int bb0 = r0 >> 11, t0 = r0 & (TSEQ - 1);
                const int r1 = r0 + 8;
                const int bb1 = r1 >> 11, t1 = r1 & (TSEQ - 1);
                *(uint32_t*)(dst + (((size_t)bb0 * NH + h) * TSEQ + t0) * HD + d0) = pack_h2(e0, e1);
                *(uint32_t*)(dst + (((size_t)bb1 * NH + h) * TSEQ + t1) * HD + d0) = pack_h2(e2, e3);
            } else {
                *(float2*)(out + (size_t)r0 * CDIM + n0 + cb_loc) = make_float2(e0, e1);
                *(float2*)(out + (size_t)(r0 + 8) * CDIM + n0 + cb_loc) = make_float2(e2, e3);
            }
        }
    }
}

// ---------------------------------------------------------------------------
// Causal flash attention, fp16 mma.sync + ldmatrix, P kept in registers.
// CTA: 128 q-rows, 128 threads (4 warps x 32 rows), K-tile 64, 3-stage KV ring.
// Q [128][72]h, K/V [3][64][72]h each.
// ---------------------------------------------------------------------------
#define QPH 72
#define ATT_Q_BY (128 * QPH * 2)        // 18432
#define ATT_T_BY (64 * QPH * 2)         // 9216 per K or V stage
#define ATT_SMEM (ATT_Q_BY + 6 * ATT_T_BY)   // 73728

__global__ __launch_bounds__(128, 2) void attn_tc_kernel()
{
    extern __shared__ __align__(16) char smc[];
    const uint32_t sb  = smem_u32(smc);
    const uint32_t qb  = sb;
    const uint32_t kb0 = sb + ATT_Q_BY;
    const uint32_t vb0 = kb0 + 3 * ATT_T_BY;

    const int tid  = threadIdx.x;
    const int lane = tid & 31;
    const int w    = tid >> 5;
    const int qi   = (int)(gridDim.x - 1 - blockIdx.x);   // LPT
    const int bh   = blockIdx.y;

    const size_t hoff = (size_t)bh * TSEQ * HD;
    const __half* Qg = g_q + hoff + (size_t)qi * 128 * HD;
    const __half* Kg = g_k + hoff;
    const __half* Vg = g_v + hoff;

    const int nkt = 2 * qi + 2;

#define FKV(slot, kt) do {                                                      \
    const uint32_t kb_ = kb0 + (uint32_t)(slot) * ATT_T_BY;                     \
    const uint32_t vb_ = vb0 + (uint32_t)(slot) * ATT_T_BY;                     \
    const __half* kp = Kg + (size_t)(kt) * 64 * HD;                             \
    const __half* vp = Vg + (size_t)(kt) * 64 * HD;                             \
    _Pragma("unroll")                                                           \
    for (int u = 0; u < 4; u++) {                                               \
        const int idx = tid + u * 128;                                          \
        const int r = idx >> 3, g = idx & 7;                                    \
        cpa16(kb_ + (uint32_t)(r * QPH + g * 8) * 2, kp + (size_t)r * HD + g * 8); \
        cpa16(vb_ + (uint32_t)(r * QPH + g * 8) * 2, vp + (size_t)r * HD + g * 8); \
    }                                                                           \
} while (0)

    // prologue: Q (group0), KV0 (group1), KV1 (group2)
#pragma unroll
    for (int u = 0; u < 8; u++) {
        const int idx = tid + u * 128;
        const int r = idx >> 3, g = idx & 7;
        cpa16(qb + (uint32_t)(r * QPH + g * 8) * 2, Qg + (size_t)r * HD + g * 8);
    }
    CPA_COMMIT();
    FKV(0, 0); CPA_COMMIT();
    if (nkt > 1) FKV(1, 1);
    CPA_COMMIT();

    cpa_wait<2>();          // Q ready
    __syncthreads();

    const int r8 = lane & 7, q4 = lane >> 3;
    // A-pattern (x4): row = base + (q&1)*8 + r8, col = kk + (q>>1)*8
    const uint32_t qa_base = (uint32_t)((w * 32 + r8 + (q4 & 1) * 8) * QPH
                                        + (q4 >> 1) * 8) * 2;
    // K (x4 non-trans): row = n + (q>>1)*8 + r8, col = kk + (q&1)*8
    const uint32_t kb_base = (uint32_t)(((q4 >> 1) * 8 + r8) * QPH + (q4 & 1) * 8) * 2;
    // V (x4 trans): row = kk + (q&1)*8 + r8, col = d + (q>>1)*8
    const uint32_t vb_base = (uint32_t)(((q4 & 1) * 8 + r8) * QPH + (q4 >> 1) * 8) * 2;

    // Q fragments (held in registers all loop; Q pre-scaled by 1/8 in QKV epi)
    uint32_t qf[2][4][4];
#pragma unroll
    for (int mf = 0; mf < 2; mf++)
#pragma unroll
        for (int kf = 0; kf < 4; kf++)
            ldsm_x4(qf[mf][kf], qb + qa_base + (uint32_t)(mf * 16 * QPH + kf * 16) * 2);

    float o[2][8][4];
#pragma unroll
    for (int mf = 0; mf < 2; mf++)
#pragma unroll
        for (int nf = 0; nf < 8; nf++)
#pragma unroll
            for (int e = 0; e < 4; e++) o[mf][nf][e] = 0.f;
    float mrow[2][2] = {{-INFINITY, -INFINITY}, {-INFINITY, -INFINITY}};
    float lrow[2][2] = {{0.f, 0.f}, {0.f, 0.f}};

    for (int kt = 0; kt < nkt; kt++) {
        cpa_wait<1>();      // KV stage kt ready
        __syncthreads();
        if (kt + 2 < nkt) FKV((kt + 2) % 3, kt + 2);
        CPA_COMMIT();

        const uint32_t kb = kb0 + (uint32_t)(kt % 3) * ATT_T_BY;
        const uint32_t vb = vb0 + (uint32_t)(kt % 3) * ATT_T_BY;

        // ---- S = Q @ K^T ----
        float s[2][8][4];
#pragma unroll
        for (int mf = 0; mf < 2; mf++)
#pragma unroll
            for (int nf = 0; nf < 8; nf++)
#pragma unroll
                for (int e = 0; e < 4; e++) s[mf][nf][e] = 0.f;

#pragma unroll
        for (int kf = 0; kf < 4; kf++) {
            uint32_t bfr[4][4];
#pragma unroll
            for (int np = 0; np < 4; np++)
                ldsm_x4(bfr[np], kb + kb_base + (uint32_t)(np * 16 * QPH + kf * 16) * 2);
#pragma unroll
            for (int mf = 0; mf < 2; mf++)
#pragma unroll
                for (int nf = 0; nf < 8; nf++)
                    mma_f16(s[mf][nf], qf[mf][kf], &bfr[nf >> 1][(nf & 1) * 2]);
        }

        // ---- causal mask (only the two diagonal tiles) ----
        if (kt >= nkt - 2) {
#pragma unroll
            for (int mf = 0; mf < 2; mf++) {
                const int rb = qi * 128 + w * 32 + mf * 16 + (lane >> 2);
#pragma unroll
                for (int nf = 0; nf < 8; nf++) {
                    const int cg = kt * 64 + nf * 8 + 2 * (lane & 3);
                    if (cg     > rb)     s[mf][nf][0] = -INFINITY;
                    if (cg + 1 > rb)     s[mf][nf][1] = -INFINITY;
                    if (cg     > rb + 8) s[mf][nf][2] = -INFINITY;
                    if (cg + 1 > rb + 8) s[mf][nf][3] = -INFINITY;
                }
            }
        }

        // ---- online softmax; P packed to fp16 in registers ----
        uint32_t pa[2][4][4];
#pragma unroll
        for (int mf = 0; mf < 2; mf++) {
            float rm0 = -INFINITY, rm1 = -INFINITY;
#pragma unroll
            for (int nf = 0; nf < 8; nf++) {
                rm0 = fmaxf(rm0, fmaxf(s[mf][nf][0], s[mf][nf][1]));
                rm1 = fmaxf(rm1, fmaxf(s[mf][nf][2], s[mf][nf][3]));
            }
            rm0 = fmaxf(rm0, __shfl_xor_sync(0xFFFFFFFF, rm0, 1));
            rm0 = fmaxf(rm0, __shfl_xor_sync(0xFFFFFFFF, rm0, 2));
            rm1 = fmaxf(rm1, __shfl_xor_sync(0xFFFFFFFF, rm1, 1));
            rm1 = fmaxf(rm1, __shfl_xor_sync(0xFFFFFFFF, rm1, 2));
            const float mn0 = fmaxf(mrow[mf][0], rm0);
            const float mn1 = fmaxf(mrow[mf][1], rm1);
            const float c0 = __expf(mrow[mf][0] - mn0);
            const float c1 = __expf(mrow[mf][1] - mn1);
            mrow[mf][0] = mn0; mrow[mf][1] = mn1;
            float rs0 = 0.f, rs1 = 0.f;
#pragma unroll
            for (int nf = 0; nf < 8; nf++) {
                const float p0 = __expf(s[mf][nf][0] - mn0);
                const float p1 = __expf(s[mf][nf][1] - mn0);
                const float p2 = __expf(s[mf][nf][2] - mn1);
                const float p3 = __expf(s[mf][nf][3] - mn1);
                rs0 += p0 + p1; rs1 += p2 + p3;
                o[mf][nf][0] *= c0; o[mf][nf][1] *= c0;
                o[mf][nf][2] *= c1; o[mf][nf][3] *= c1;
                s[mf][nf][0] = p0; s[mf][nf][1] = p1;
                s[mf][nf][2] = p2; s[mf][nf][3] = p3;
            }
            rs0 += __shfl_xor_sync(0xFFFFFFFF, rs0, 1);
            rs0 += __shfl_xor_sync(0xFFFFFFFF, rs0, 2);
            rs1 += __shfl_xor_sync(0xFFFFFFFF, rs1, 1);
            rs1 += __shfl_xor_sync(0xFFFFFFFF, rs1, 2);
            lrow[mf][0] = lrow[mf][0] * c0 + rs0;
            lrow[mf][1] = lrow[mf][1] * c1 + rs1;
            // D-frag -> A-frag register remap (no smem round-trip)
#pragma unroll
            for (int j = 0; j < 4; j++) {
                pa[mf][j][0] = pack_h2(s[mf][2 * j][0],     s[mf][2 * j][1]);
                pa[mf][j][1] = pack_h2(s[mf][2 * j][2],     s[mf][2 * j][3]);
                pa[mf][j][2] = pack_h2(s[mf][2 * j + 1][0], s[mf][2 * j + 1][1]);
                pa[mf][j][3] = pack_h2(s[mf][2 * j + 1][2], s[mf][2 * j + 1][3]);
            }
        }

        // ---- O += P @ V ----
#pragma unroll
        for (int kf = 0; kf < 4; kf++) {
            uint32_t vfr[4][4];
#pragma unroll
            for (int dp = 0; dp < 4; dp++)
                ldsm_x4t(vfr[dp], vb + vb_base + (uint32_t)(kf * 16 * QPH + dp * 16) * 2);
#pragma unroll
            for (int mf = 0; mf < 2; mf++)
#pragma unroll
                for (int nf = 0; nf < 8; nf++)
                    mma_f16(o[mf][nf], pa[mf][kf], &vfr[nf >> 1][(nf & 1) * 2]);
        }
    }
#undef FKV

    // ---- normalize + write g_y (half) ----
    const int b = bh >> 4;
    const int h = bh & 15;
#pragma unroll
    for (int mf = 0; mf < 2; mf++) {
        const float inv0 = 1.0f / lrow[mf][0];
        const float inv1 = 1.0f / lrow[mf][1];
        const int t0 = qi * 128 + w * 32 + mf * 16 + (lane >> 2);
        __half* y0 = g_y + ((size_t)b * TSEQ + t0) * CDIM + h * 64;
        __half* y1 = g_y + ((size_t)b * TSEQ + t0 + 8) * CDIM + h * 64;
#pragma unroll
        for (int nf = 0; nf < 8; nf++) {
            const int c = nf * 8 + 2 * (lane & 3);
            *(uint32_t*)(y0 + c) = pack_h2(o[mf][nf][0] * inv0, o[mf][nf][1] * inv0);
            *(uint32_t*)(y1 + c) = pack_h2(o[mf][nf][2] * inv1, o[mf][nf][3] * inv1);
        }
    }
}

// ---------------------------------------------------------------------------
extern "C" void kernel_launch(void* const* d_in, const int* in_sizes, int n_in,
                              void* d_out, int out_size)
{
    const float* x      = (const float*)d_in[0];
    const float* W_attn = (const float*)d_in[1];
    const float* b_attn = (const float*)d_in[2];
    const float* W_proj = (const float*)d_in[3];
    const float* b_proj = (const float*)d_in[4];
    float* out = (float*)d_out;

    static bool attr_set = false;
    if (!attr_set) {
        cudaFuncSetAttribute(attn_tc_kernel,
                             cudaFuncAttributeMaxDynamicSharedMemorySize, ATT_SMEM);
        cudaFuncSetAttribute((const void*)tc_gemm_kernel<0>,
                             cudaFuncAttributeMaxDynamicSharedMemorySize, GEMM_DYN);
        cudaFuncSetAttribute((const void*)tc_gemm_kernel<1>,
                             cudaFuncAttributeMaxDynamicSharedMemorySize, GEMM_DYN);
        attr_set = true;
    }

    // 0) fp32 -> fp16 operand prep
    to_half_kernel<0><<<(MROWS * CDIM / 8 + 255) / 256, 256>>>(x, MROWS * CDIM / 8);
    to_half_kernel<1><<<(CDIM * N3 / 8 + 255) / 256, 256>>>(W_attn, CDIM * N3 / 8);
    to_half_kernel<2><<<(CDIM * CDIM / 8 + 255) / 256, 256>>>(W_proj, CDIM * CDIM / 8);

    // 1) QKV GEMM
    {
        dim3 grid(N3 / BN, MROWS / BM);
        tc_gemm_kernel<0><<<grid, 256, GEMM_DYN>>>(b_attn, nullptr);
    }
    // 2) Flash attention
    {
        dim3 grid(TSEQ / 128, BSZ * NH);
        attn_tc_kernel<<<grid, 128, ATT_SMEM>>>();
    }
    // 3) Projection GEMM
    {
        dim3 grid(CDIM / BN, MROWS / BM);
        tc_gemm_kernel<1><<<grid, 256, GEMM_DYN>>>(b_proj, out);
    }
}

// round 9
// speedup vs baseline: 1.8969x; 1.0094x over previous
#include <cuda_runtime.h>
#include <cuda_fp16.h>
#include <math.h>
#include <stdint.h>

// Problem constants
#define BSZ   2
#define TSEQ  2048
#define NH    16
#define HD    64
#define CDIM  1024
#define N3    (3 * CDIM)
#define MROWS (BSZ * TSEQ)          // 4096

// Scratch (device globals; all fp16 operands)
__device__ __half g_q[(size_t)BSZ * NH * TSEQ * HD];
__device__ __half g_k[(size_t)BSZ * NH * TSEQ * HD];
__device__ __half g_v[(size_t)BSZ * NH * TSEQ * HD];
__device__ __half g_y[(size_t)MROWS * CDIM];
__device__ __half g_x[(size_t)MROWS * CDIM];
__device__ __half g_wattn[(size_t)CDIM * N3];
__device__ __half g_wproj[(size_t)CDIM * CDIM];

// ---------------------------------------------------------------------------
// helpers
// ---------------------------------------------------------------------------
__device__ __forceinline__ uint32_t smem_u32(const void* p) {
    uint32_t a;
    asm("{ .reg .u64 t; cvta.to.shared.u64 t, %1; cvt.u32.u64 %0, t; }"
        : "=r"(a) : "l"(p));
    return a;
}
__device__ __forceinline__ void cpa16(uint32_t dst, const void* src) {
    asm volatile("cp.async.cg.shared.global [%0], [%1], 16;"
                 :: "r"(dst), "l"(src));
}
#define CPA_COMMIT() asm volatile("cp.async.commit_group;" ::: "memory")
template <int N>
__device__ __forceinline__ void cpa_wait() {
    asm volatile("cp.async.wait_group %0;" :: "n"(N) : "memory");
}
__device__ __forceinline__ void ldsm_x4(uint32_t* r, uint32_t addr) {
    asm volatile("ldmatrix.sync.aligned.m8n8.x4.shared.b16 {%0,%1,%2,%3}, [%4];"
                 : "=r"(r[0]), "=r"(r[1]), "=r"(r[2]), "=r"(r[3]) : "r"(addr));
}
__device__ __forceinline__ void ldsm_x4t(uint32_t* r, uint32_t addr) {
    asm volatile("ldmatrix.sync.aligned.m8n8.x4.trans.shared.b16 {%0,%1,%2,%3}, [%4];"
                 : "=r"(r[0]), "=r"(r[1]), "=r"(r[2]), "=r"(r[3]) : "r"(addr));
}
__device__ __forceinline__ void mma_f16(float* d, const uint32_t* a, const uint32_t* b) {
    asm volatile(
        "mma.sync.aligned.m16n8k16.row.col.f32.f16.f16.f32 "
        "{%0,%1,%2,%3}, {%4,%5,%6,%7}, {%8,%9}, {%0,%1,%2,%3};"
        : "+f"(d[0]), "+f"(d[1]), "+f"(d[2]), "+f"(d[3])
        : "r"(a[0]), "r"(a[1]), "r"(a[2]), "r"(a[3]), "r"(b[0]), "r"(b[1]));
}
__device__ __forceinline__ uint32_t pack_h2(float a, float b) {
    __half2 h = __floats2half2_rn(a, b);
    return *reinterpret_cast<uint32_t*>(&h);
}

// ---------------------------------------------------------------------------
// Prep: one kernel converts x, W_attn, W_proj to fp16 (range-split grid).
// Sizes in float4-pairs (8 floats per thread):
//   x: 524288, W_attn: 393216, W_proj: 131072  -> total 1048576 threads
// ---------------------------------------------------------------------------
#define NX8 (MROWS * CDIM / 8)       // 524288
#define NA8 (CDIM * N3 / 8)          // 393216
#define NP8 (CDIM * CDIM / 8)        // 131072

__global__ __launch_bounds__(256) void to_half_all_kernel(
    const float* __restrict__ x, const float* __restrict__ wa,
    const float* __restrict__ wp)
{
    int i = blockIdx.x * blockDim.x + threadIdx.x;
    const float* src;
    __half* dst;
    if (i < NX8) { src = x; dst = g_x; }
    else if (i < NX8 + NA8) { i -= NX8; src = wa; dst = g_wattn; }
    else { i -= NX8 + NA8; src = wp; dst = g_wproj; }
    float4 a = ((const float4*)src)[2 * i];
    float4 b = ((const float4*)src)[2 * i + 1];
    uint4 p;
    p.x = pack_h2(a.x, a.y); p.y = pack_h2(a.z, a.w);
    p.z = pack_h2(b.x, b.y); p.w = pack_h2(b.z, b.w);
    ((uint4*)dst)[i] = p;
}

// ---------------------------------------------------------------------------
// fp16 mma.sync GEMM, 4-stage cp.async pipeline, ldmatrix fragments.
// CTA 128x256, 512 threads: 16 warps (4m x 4n), warp tile 32x64. BK=32.
// A smem [128][40]h, B smem [32][264]h.
// MODE 0: A=g_x, W=g_wattn -> scatter q(*0.125)/k/v (half)
// MODE 1: A=g_y, W=g_wproj -> out (fp32)
// ---------------------------------------------------------------------------
#define BM 128
#define BN 256
#define BK 32
#define NCHUNK  (CDIM / BK)            // 32
#define APH 40
#define BPH 264
#define A_BY (BM * APH * 2)            // 10240
#define B_BY (BK * BPH * 2)            // 16896
#define ST_BY (A_BY + B_BY)            // 27136
#define GEMM_DYN (4 * ST_BY)           // 108544

template <int MODE>
__global__ __launch_bounds__(512)
void tc_gemm_kernel(const float* __restrict__ bias, float* __restrict__ out)
{
    extern __shared__ __align__(16) char smc[];
    __shared__ float sbias[BN];
    const uint32_t sb = smem_u32(smc);

    const __half* __restrict__ A = (MODE == 0) ? g_x : g_y;
    const __half* __restrict__ W = (MODE == 0) ? g_wattn : g_wproj;
    const int ldb = (MODE == 0) ? N3 : CDIM;

    const int tid    = threadIdx.x;
    const int lane   = tid & 31;
    const int wid    = tid >> 5;
    const int warp_m = wid & 3;            // 4 x 32 rows
    const int warp_n = wid >> 2;           // 4 x 64 cols
    const int m0 = blockIdx.y * BM;
    const int n0 = blockIdx.x * BN;

    if (tid < BN) sbias[tid] = bias[n0 + tid];

    float acc[2][8][4];
#pragma unroll
    for (int mf = 0; mf < 2; mf++)
#pragma unroll
        for (int nf = 0; nf < 8; nf++)
#pragma unroll
            for (int r = 0; r < 4; r++) acc[mf][nf][r] = 0.f;

#define GF(slot, k0) do {                                                       \
    const uint32_t ab_ = sb + (uint32_t)(slot) * ST_BY;                         \
    const uint32_t bb_ = ab_ + A_BY;                                            \
    {                                                                           \
        const int row = tid >> 2, g = tid & 3;                                  \
        cpa16(ab_ + (uint32_t)(row * APH + g * 8) * 2,                          \
              A + (size_t)(m0 + row) * CDIM + (k0) + g * 8);                    \
    }                                                                           \
    _Pragma("unroll")                                                           \
    for (int u = 0; u < 2; u++) {                                               \
        const int idx = tid + u * 512;                                          \
        const int row = idx >> 5, g = idx & 31;                                 \
        cpa16(bb_ + (uint32_t)(row * BPH + g * 8) * 2,                          \
              W + (size_t)((k0) + row) * ldb + n0 + g * 8);                     \
    }                                                                           \
} while (0)

    GF(0, 0);      CPA_COMMIT();
    GF(1, BK);     CPA_COMMIT();
    GF(2, 2 * BK); CPA_COMMIT();

    const int r8 = lane & 7, q4 = lane >> 3;
    // A (x4, row-major): rows warp_m*32 + mf*16 + {0..15}, cols kk + {0..15}
    const uint32_t a_base = (uint32_t)((warp_m * 32 + r8 + (q4 & 1) * 8) * APH
                                       + (q4 >> 1) * 8) * 2;
    // B (x4.trans on [k][n]): rows kk+{0..15}, cols warp_n*64 + np*16 + {0..15}
    const uint32_t b_base = (uint32_t)(((q4 & 1) * 8 + r8) * BPH
                                       + warp_n * 64 + (q4 >> 1) * 8) * 2;

    for (int i = 0; i < NCHUNK; i++) {
        cpa_wait<2>();
        __syncthreads();
        if (i + 3 < NCHUNK) GF((i + 3) & 3, (i + 3) * BK);
        CPA_COMMIT();

        const uint32_t ab = sb + (uint32_t)(i & 3) * ST_BY;
        const uint32_t bb = ab + A_BY;
#pragma unroll
        for (int kk = 0; kk < BK; kk += 16) {
            uint32_t a[2][4], b[4][4];
#pragma unroll
            for (int mf = 0; mf < 2; mf++)
                ldsm_x4(a[mf], ab + a_base + (uint32_t)(mf * 16 * APH + kk) * 2);
#pragma unroll
            for (int np = 0; np < 4; np++)
                ldsm_x4t(b[np], bb + b_base + (uint32_t)(kk * BPH + np * 16) * 2);
#pragma unroll
            for (int mf = 0; mf < 2; mf++)
#pragma unroll
                for (int nf = 0; nf < 8; nf++)
                    mma_f16(acc[mf][nf], a[mf], &b[nf >> 1][(nf & 1) * 2]);
        }
    }
#undef GF

    // ---- epilogue ----
#pragma unroll
    for (int mf = 0; mf < 2; mf++) {
        const int r0 = m0 + warp_m * 32 + mf * 16 + (lane >> 2);
#pragma unroll
        for (int nf = 0; nf < 8; nf++) {
            const int cb_loc = warp_n * 64 + nf * 8 + 2 * (lane & 3);
            const float b0 = sbias[cb_loc], b1 = sbias[cb_loc + 1];
            float e0 = acc[mf][nf][0] + b0, e1 = acc[mf][nf][1] + b1;
            float e2 = acc[mf][nf][2] + b0, e3 = acc[mf][nf][3] + b1;
            if (MODE == 0) {
                const int col = n0 + cb_loc;
                const int sec = col >> 10;
                if (sec == 0) { e0 *= 0.125f; e1 *= 0.125f; e2 *= 0.125f; e3 *= 0.125f; }
                const int c   = col & (CDIM - 1);
                const int h   = c >> 6;
                const int d0  = c & (HD - 1);
                __half* dst = (sec == 0) ? g_q : ((sec == 1) ? g_k : g_v);
                const int bb0 = r0 >> 11, t0 = r0 & (TSEQ - 1);
                const int r1 = r0 + 8;
                const int bb1 = r1 >> 11, t1 = r1 & (TSEQ - 1);
                *(uint32_t*)(dst + (((size_t)bb0 * NH + h) * TSEQ + t0) * HD + d0) = pack_h2(e0, e1);
                *(uint32_t*)(dst + (((size_t)bb1 * NH + h) * TSEQ + t1) * HD + d0) = pack_h2(e2, e3);
            } else {
                *(float2*)(out + (size_t)r0 * CDIM + n0 + cb_loc) = make_float2(e0, e1);
                *(float2*)(out + (size_t)(r0 + 8) * CDIM + n0 + cb_loc) = make_float2(e2, e3);
            }
        }
    }
}

// ---------------------------------------------------------------------------
// Causal flash attention (unchanged from R8): fp16 mma.sync + ldmatrix,
// P in registers. 128 threads (4 warps x 32 rows), K-tile 64, 3-stage KV ring.
// ---------------------------------------------------------------------------
#define QPH 72
#define ATT_Q_BY (128 * QPH * 2)        // 18432
#define ATT_T_BY (64 * QPH * 2)         // 9216 per K or V stage
#define ATT_SMEM (ATT_Q_BY + 6 * ATT_T_BY)   // 73728

__global__ __launch_bounds__(128, 2) void attn_tc_kernel()
{
    extern __shared__ __align__(16) char smc[];
    const uint32_t sb  = smem_u32(smc);
    const uint32_t qb  = sb;
    const uint32_t kb0 = sb + ATT_Q_BY;
    const uint32_t vb0 = kb0 + 3 * ATT_T_BY;

    const int tid  = threadIdx.x;
    const int lane = tid & 31;
    const int w    = tid >> 5;
    const int qi   = (int)(gridDim.x - 1 - blockIdx.x);   // LPT
    const int bh   = blockIdx.y;

    const size_t hoff = (size_t)bh * TSEQ * HD;
    const __half* Qg = g_q + hoff + (size_t)qi * 128 * HD;
    const __half* Kg = g_k + hoff;
    const __half* Vg = g_v + hoff;

    const int nkt = 2 * qi + 2;

#define FKV(slot, kt) do {                                                      \
    const uint32_t kb_ = kb0 + (uint32_t)(slot) * ATT_T_BY;                     \
    const uint32_t vb_ = vb0 + (uint32_t)(slot) * ATT_T_BY;                     \
    const __half* kp = Kg + (size_t)(kt) * 64 * HD;                             \
    const __half* vp = Vg + (size_t)(kt) * 64 * HD;                             \
    _Pragma("unroll")                                                           \
    for (int u = 0; u < 4; u++) {                                               \
        const int idx = tid + u * 128;                                          \
        const int r = idx >> 3, g = idx & 7;                                    \
        cpa16(kb_ + (uint32_t)(r * QPH + g * 8) * 2, kp + (size_t)r * HD + g * 8); \
        cpa16(vb_ + (uint32_t)(r * QPH + g * 8) * 2, vp + (size_t)r * HD + g * 8); \
    }                                                                           \
} while (0)

#pragma unroll
    for (int u = 0; u < 8; u++) {
        const int idx = tid + u * 128;
        const int r = idx >> 3, g = idx & 7;
        cpa16(qb + (uint32_t)(r * QPH + g * 8) * 2, Qg + (size_t)r * HD + g * 8);
    }
    CPA_COMMIT();
    FKV(0, 0); CPA_COMMIT();
    if (nkt > 1) FKV(1, 1);
    CPA_COMMIT();

    cpa_wait<2>();
    __syncthreads();

    const int r8 = lane & 7, q4 = lane >> 3;
    const uint32_t qa_base = (uint32_t)((w * 32 + r8 + (q4 & 1) * 8) * QPH
                                        + (q4 >> 1) * 8) * 2;
    const uint32_t kb_base = (uint32_t)(((q4 >> 1) * 8 + r8) * QPH + (q4 & 1) * 8) * 2;
    const uint32_t vb_base = (uint32_t)(((q4 & 1) * 8 + r8) * QPH + (q4 >> 1) * 8) * 2;

    uint32_t qf[2][4][4];
#pragma unroll
    for (int mf = 0; mf < 2; mf++)
#pragma unroll
        for (int kf = 0; kf < 4; kf++)
            ldsm_x4(qf[mf][kf], qb + qa_base + (uint32_t)(mf * 16 * QPH + kf * 16) * 2);

    float o[2][8][4];
#pragma unroll
    for (int mf = 0; mf < 2; mf++)
#pragma unroll
        for (int nf = 0; nf < 8; nf++)
#pragma unroll
            for (int e = 0; e < 4; e++) o[mf][nf][e] = 0.f;
    float mrow[2][2] = {{-INFINITY, -INFINITY}, {-INFINITY, -INFINITY}};
    float lrow[2][2] = {{0.f, 0.f}, {0.f, 0.f}};

    for (int kt = 0; kt < nkt; kt++) {
        cpa_wait<1>();
        __syncthreads();
        if (kt + 2 < nkt) FKV((kt + 2) % 3, kt + 2);
        CPA_COMMIT();

        const uint32_t kb = kb0 + (uint32_t)(kt % 3) * ATT_T_BY;
        const uint32_t vb = vb0 + (uint32_t)(kt % 3) * ATT_T_BY;

        float s[2][8][4];
#pragma unroll
        for (int mf = 0; mf < 2; mf++)
#pragma unroll
            for (int nf = 0; nf < 8; nf++)
#pragma unroll
                for (int e = 0; e < 4; e++) s[mf][nf][e] = 0.f;

#pragma unroll
        for (int kf = 0; kf < 4; kf++) {
            uint32_t bfr[4][4];
#pragma unroll
            for (int np = 0; np < 4; np++)
                ldsm_x4(bfr[np], kb + kb_base + (uint32_t)(np * 16 * QPH + kf * 16) * 2);
#pragma unroll
            for (int mf = 0; mf < 2; mf++)
#pragma unroll
                for (int nf = 0; nf < 8; nf++)
                    mma_f16(s[mf][nf], qf[mf][kf], &bfr[nf >> 1][(nf & 1) * 2]);
        }

        if (kt >= nkt - 2) {
#pragma unroll
            for (int mf = 0; mf < 2; mf++) {
                const int rb = qi * 128 + w * 32 + mf * 16 + (lane >> 2);
#pragma unroll
                for (int nf = 0; nf < 8; nf++) {
                    const int cg = kt * 64 + nf * 8 + 2 * (lane & 3);
                    if (cg     > rb)     s[mf][nf][0] = -INFINITY;
                    if (cg + 1 > rb)     s[mf][nf][1] = -INFINITY;
                    if (cg     > rb + 8) s[mf][nf][2] = -INFINITY;
                    if (cg + 1 > rb + 8) s[mf][nf][3] = -INFINITY;
                }
            }
        }

        uint32_t pa[2][4][4];
#pragma unroll
        for (int mf = 0; mf < 2; mf++) {
            float rm0 = -INFINITY, rm1 = -INFINITY;
#pragma unroll
            for (int nf = 0; nf < 8; nf++) {
                rm0 = fmaxf(rm0, fmaxf(s[mf][nf][0], s[mf][nf][1]));
                rm1 = fmaxf(rm1, fmaxf(s[mf][nf][2], s[mf][nf][3]));
            }
            rm0 = fmaxf(rm0, __shfl_xor_sync(0xFFFFFFFF, rm0, 1));
            rm0 = fmaxf(rm0, __shfl_xor_sync(0xFFFFFFFF, rm0, 2));
            rm1 = fmaxf(rm1, __shfl_xor_sync(0xFFFFFFFF, rm1, 1));
            rm1 = fmaxf(rm1, __shfl_xor_sync(0xFFFFFFFF, rm1, 2));
            const float mn0 = fmaxf(mrow[mf][0], rm0);
            const float mn1 = fmaxf(mrow[mf][1], rm1);
            const float c0 = __expf(mrow[mf][0] - mn0);
            const float c1 = __expf(mrow[mf][1] - mn1);
            mrow[mf][0] = mn0; mrow[mf][1] = mn1;
            float rs0 = 0.f, rs1 = 0.f;
#pragma unroll
            for (int nf = 0; nf < 8; nf++) {
                const float p0 = __expf(s[mf][nf][0] - mn0);
                const float p1 = __expf(s[mf][nf][1] - mn0);
                const float p2 = __expf(s[mf][nf][2] - mn1);
                const float p3 = __expf(s[mf][nf][3] - mn1);
                rs0 += p0 + p1; rs1 += p2 + p3;
                o[mf][nf][0] *= c0; o[mf][nf][1] *= c0;
                o[mf][nf][2] *= c1; o[mf][nf][3] *= c1;
                s[mf][nf][0] = p0; s[mf][nf][1] = p1;
                s[mf][nf][2] = p2; s[mf][nf][3] = p3;
            }
            rs0 += __shfl_xor_sync(0xFFFFFFFF, rs0, 1);
            rs0 += __shfl_xor_sync(0xFFFFFFFF, rs0, 2);
            rs1 += __shfl_xor_sync(0xFFFFFFFF, rs1, 1);
            rs1 += __shfl_xor_sync(0xFFFFFFFF, rs1, 2);
            lrow[mf][0] = lrow[mf][0] * c0 + rs0;
            lrow[mf][1] = lrow[mf][1] * c1 + rs1;
#pragma unroll
            for (int j = 0; j < 4; j++) {
                pa[mf][j][0] = pack_h2(s[mf][2 * j][0],     s[mf][2 * j][1]);
                pa[mf][j][1] = pack_h2(s[mf][2 * j][2],     s[mf][2 * j][3]);
                pa[mf][j][2] = pack_h2(s[mf][2 * j + 1][0], s[mf][2 * j + 1][1]);
                pa[mf][j][3] = pack_h2(s[mf][2 * j + 1][2], s[mf][2 * j + 1][3]);
            }
        }

#pragma unroll
        for (int kf = 0; kf < 4; kf++) {
            uint32_t vfr[4][4];
#pragma unroll
            for (int dp = 0; dp < 4; dp++)
                ldsm_x4t(vfr[dp], vb + vb_base + (uint32_t)(kf * 16 * QPH + dp * 16) * 2);
#pragma unroll
            for (int mf = 0; mf < 2; mf++)
#pragma unroll
                for (int nf = 0; nf < 8; nf++)
                    mma_f16(o[mf][nf], pa[mf][kf], &vfr[nf >> 1][(nf & 1) * 2]);
        }
    }
#undef FKV

    const int b = bh >> 4;
    const int h = bh & 15;
#pragma unroll
    for (int mf = 0; mf < 2; mf++) {
        const float inv0 = 1.0f / lrow[mf][0];
        const float inv1 = 1.0f / lrow[mf][1];
        const int t0 = qi * 128 + w * 32 + mf * 16 + (lane >> 2);
        __half* y0 = g_y + ((size_t)b * TSEQ + t0) * CDIM + h * 64;
        __half* y1 = g_y + ((size_t)b * TSEQ + t0 + 8) * CDIM + h * 64;
#pragma unroll
        for (int nf = 0; nf < 8; nf++) {
            const int c = nf * 8 + 2 * (lane & 3);
            *(uint32_t*)(y0 + c) = pack_h2(o[mf][nf][0] * inv0, o[mf][nf][1] * inv0);
            *(uint32_t*)(y1 + c) = pack_h2(o[mf][nf][2] * inv1, o[mf][nf][3] * inv1);
        }
    }
}

// ---------------------------------------------------------------------------
extern "C" void kernel_launch(void* const* d_in, const int* in_sizes, int n_in,
                              void* d_out, int out_size)
{
    const float* x      = (const float*)d_in[0];
    const float* W_attn = (const float*)d_in[1];
    const float* b_attn = (const float*)d_in[2];
    const float* W_proj = (const float*)d_in[3];
    const float* b_proj = (const float*)d_in[4];
    float* out = (float*)d_out;

    static bool attr_set = false;
    if (!attr_set) {
        cudaFuncSetAttribute(attn_tc_kernel,
                             cudaFuncAttributeMaxDynamicSharedMemorySize, ATT_SMEM);
        cudaFuncSetAttribute((const void*)tc_gemm_kernel<0>,
                             cudaFuncAttributeMaxDynamicSharedMemorySize, GEMM_DYN);
        cudaFuncSetAttribute((const void*)tc_gemm_kernel<1>,
                             cudaFuncAttributeMaxDynamicSharedMemorySize, GEMM_DYN);
        attr_set = true;
    }

    // 0) fp32 -> fp16 operand prep (single launch)
    to_half_all_kernel<<<(NX8 + NA8 + NP8) / 256, 256>>>(x, W_attn, W_proj);

    // 1) QKV GEMM
    {
        dim3 grid(N3 / BN, MROWS / BM);
        tc_gemm_kernel<0><<<grid, 512, GEMM_DYN>>>(b_attn, nullptr);
    }
    // 2) Flash attention
    {
        dim3 grid(TSEQ / 128, BSZ * NH);
        attn_tc_kernel<<<grid, 128, ATT_SMEM>>>();
    }
    // 3) Projection GEMM
    {
        dim3 grid(CDIM / BN, MROWS / BM);
        tc_gemm_kernel<1><<<grid, 512, GEMM_DYN>>>(b_proj, out);
    }
}

// round 10
// speedup vs baseline: 2.0367x; 1.0737x over previous
#include <cuda_runtime.h>
#include <cuda_fp16.h>
#include <math.h>
#include <stdint.h>

// Problem constants
#define BSZ   2
#define TSEQ  2048
#define NH    16
#define HD    64
#define CDIM  1024
#define N3    (3 * CDIM)
#define MROWS (BSZ * TSEQ)          // 4096

// Scratch (device globals; all fp16 operands)
__device__ __half g_q[(size_t)BSZ * NH * TSEQ * HD];
__device__ __half g_k[(size_t)BSZ * NH * TSEQ * HD];
__device__ __half g_v[(size_t)BSZ * NH * TSEQ * HD];
__device__ __half g_y[(size_t)MROWS * CDIM];
__device__ __half g_x[(size_t)MROWS * CDIM];
__device__ __half g_wattn[(size_t)CDIM * N3];
__device__ __half g_wproj[(size_t)CDIM * CDIM];

// ---------------------------------------------------------------------------
// helpers
// ---------------------------------------------------------------------------
__device__ __forceinline__ uint32_t smem_u32(const void* p) {
    uint32_t a;
    asm("{ .reg .u64 t; cvta.to.shared.u64 t, %1; cvt.u32.u64 %0, t; }"
        : "=r"(a) : "l"(p));
    return a;
}
__device__ __forceinline__ void cpa16(uint32_t dst, const void* src) {
    asm volatile("cp.async.cg.shared.global [%0], [%1], 16;"
                 :: "r"(dst), "l"(src));
}
#define CPA_COMMIT() asm volatile("cp.async.commit_group;" ::: "memory")
template <int N>
__device__ __forceinline__ void cpa_wait() {
    asm volatile("cp.async.wait_group %0;" :: "n"(N) : "memory");
}
__device__ __forceinline__ void ldsm_x4(uint32_t* r, uint32_t addr) {
    asm volatile("ldmatrix.sync.aligned.m8n8.x4.shared.b16 {%0,%1,%2,%3}, [%4];"
                 : "=r"(r[0]), "=r"(r[1]), "=r"(r[2]), "=r"(r[3]) : "r"(addr));
}
__device__ __forceinline__ void ldsm_x4t(uint32_t* r, uint32_t addr) {
    asm volatile("ldmatrix.sync.aligned.m8n8.x4.trans.shared.b16 {%0,%1,%2,%3}, [%4];"
                 : "=r"(r[0]), "=r"(r[1]), "=r"(r[2]), "=r"(r[3]) : "r"(addr));
}
__device__ __forceinline__ void mma_f16(float* d, const uint32_t* a, const uint32_t* b) {
    asm volatile(
        "mma.sync.aligned.m16n8k16.row.col.f32.f16.f16.f32 "
        "{%0,%1,%2,%3}, {%4,%5,%6,%7}, {%8,%9}, {%0,%1,%2,%3};"
        : "+f"(d[0]), "+f"(d[1]), "+f"(d[2]), "+f"(d[3])
        : "r"(a[0]), "r"(a[1]), "r"(a[2]), "r"(a[3]), "r"(b[0]), "r"(b[1]));
}
__device__ __forceinline__ uint32_t pack_h2(float a, float b) {
    __half2 h = __floats2half2_rn(a, b);
    return *reinterpret_cast<uint32_t*>(&h);
}

// ---------------------------------------------------------------------------
// Prep: one kernel converts x, W_attn, W_proj to fp16 (range-split grid).
// ---------------------------------------------------------------------------
#define NX8 (MROWS * CDIM / 8)       // 524288
#define NA8 (CDIM * N3 / 8)          // 393216
#define NP8 (CDIM * CDIM / 8)        // 131072

__global__ __launch_bounds__(256) void to_half_all_kernel(
    const float* __restrict__ x, const float* __restrict__ wa,
    const float* __restrict__ wp)
{
    int i = blockIdx.x * blockDim.x + threadIdx.x;
    const float* src;
    __half* dst;
    if (i < NX8) { src = x; dst = g_x; }
    else if (i < NX8 + NA8) { i -= NX8; src = wa; dst = g_wattn; }
    else { i -= NX8 + NA8; src = wp; dst = g_wproj; }
    float4 a = ((const float4*)src)[2 * i];
    float4 b = ((const float4*)src)[2 * i + 1];
    uint4 p;
    p.x = pack_h2(a.x, a.y); p.y = pack_h2(a.z, a.w);
    p.z = pack_h2(b.x, b.y); p.w = pack_h2(b.z, b.w);
    ((uint4*)dst)[i] = p;
}

// ---------------------------------------------------------------------------
// fp16 mma.sync GEMM, 3-stage cp.async ring, BK=64 (half the barriers of R8).
// CTA 128x256, 256 threads: 8 warps (2m x 4n), warp tile 64x64.
// A smem [128][72]h (9 granules/row, 9%8=1 -> ldsm conflict-free)
// B smem [64][264]h (33 granules/row, 33%8=1 -> ldsm conflict-free)
// MODE 0: A=g_x, W=g_wattn -> scatter q(*0.125)/k/v (half)
// MODE 1: A=g_y, W=g_wproj -> out (fp32)
// ---------------------------------------------------------------------------
#define BM 128
#define BN 256
#define BK 64
#define NCHUNK  (CDIM / BK)            // 16
#define APH 72
#define BPH 264
#define A_BY (BM * APH * 2)            // 18432
#define B_BY (BK * BPH * 2)            // 33792
#define ST_BY (A_BY + B_BY)            // 52224
#define GEMM_DYN (3 * ST_BY)           // 156672

template <int MODE>
__global__ __launch_bounds__(256)
void tc_gemm_kernel(const float* __restrict__ bias, float* __restrict__ out)
{
    extern __shared__ __align__(16) char smc[];
    __shared__ float sbias[BN];
    const uint32_t sb = smem_u32(smc);

    const __half* __restrict__ A = (MODE == 0) ? g_x : g_y;
    const __half* __restrict__ W = (MODE == 0) ? g_wattn : g_wproj;
    const int ldb = (MODE == 0) ? N3 : CDIM;

    const int tid    = threadIdx.x;
    const int lane   = tid & 31;
    const int wid    = tid >> 5;
    const int warp_m = wid & 1;            // 2 x 64 rows
    const int warp_n = wid >> 1;           // 4 x 64 cols
    const int m0 = blockIdx.y * BM;
    const int n0 = blockIdx.x * BN;

    sbias[tid] = bias[n0 + tid];

    float acc[4][8][4];
#pragma unroll
    for (int mf = 0; mf < 4; mf++)
#pragma unroll
        for (int nf = 0; nf < 8; nf++)
#pragma unroll
            for (int r = 0; r < 4; r++) acc[mf][nf][r] = 0.f;

#define GF(slot, k0) do {                                                       \
    const uint32_t ab_ = sb + (uint32_t)(slot) * ST_BY;                         \
    const uint32_t bb_ = ab_ + A_BY;                                            \
    _Pragma("unroll")                                                           \
    for (int u = 0; u < 4; u++) {                                               \
        const int idx = tid + u * 256;                                          \
        const int row = idx >> 3, g = idx & 7;                                  \
        cpa16(ab_ + (uint32_t)(row * APH + g * 8) * 2,                          \
              A + (size_t)(m0 + row) * CDIM + (k0) + g * 8);                    \
    }                                                                           \
    _Pragma("unroll")                                                           \
    for (int u = 0; u < 8; u++) {                                               \
        const int idx = tid + u * 256;                                          \
        const int row = idx >> 5, g = idx & 31;                                 \
        cpa16(bb_ + (uint32_t)(row * BPH + g * 8) * 2,                          \
              W + (size_t)((k0) + row) * ldb + n0 + g * 8);                     \
    }                                                                           \
} while (0)

    GF(0, 0);  CPA_COMMIT();
    GF(1, BK); CPA_COMMIT();

    const int r8 = lane & 7, q4 = lane >> 3;
    // A (x4, row-major): rows warp_m*64 + mf*16 + {0..15}, cols kk + {0..15}
    const uint32_t a_base = (uint32_t)((warp_m * 64 + r8 + (q4 & 1) * 8) * APH
                                       + (q4 >> 1) * 8) * 2;
    // B (x4.trans on [k][n]): rows kk+{0..15}, cols warp_n*64 + np*16 + {0..15}
    const uint32_t b_base = (uint32_t)(((q4 & 1) * 8 + r8) * BPH
                                       + warp_n * 64 + (q4 >> 1) * 8) * 2;

    for (int i = 0; i < NCHUNK; i++) {
        cpa_wait<1>();
        __syncthreads();
        if (i + 2 < NCHUNK) GF((i + 2) % 3, (i + 2) * BK);
        CPA_COMMIT();

        const uint32_t ab = sb + (uint32_t)(i % 3) * ST_BY;
        const uint32_t bb = ab + A_BY;
#pragma unroll
        for (int kk = 0; kk < BK; kk += 16) {
            uint32_t a[4][4], b[4][4];
#pragma unroll
            for (int mf = 0; mf < 4; mf++)
                ldsm_x4(a[mf], ab + a_base + (uint32_t)(mf * 16 * APH + kk) * 2);
#pragma unroll
            for (int np = 0; np < 4; np++)
                ldsm_x4t(b[np], bb + b_base + (uint32_t)(kk * BPH + np * 16) * 2);
#pragma unroll
            for (int mf = 0; mf < 4; mf++)
#pragma unroll
                for (int nf = 0; nf < 8; nf++)
                    mma_f16(acc[mf][nf], a[mf], &b[nf >> 1][(nf & 1) * 2]);
        }
    }
#undef GF

    // ---- epilogue ----
#pragma unroll
    for (int mf = 0; mf < 4; mf++) {
        const int r0 = m0 + warp_m * 64 + mf * 16 + (lane >> 2);
#pragma unroll
        for (int nf = 0; nf < 8; nf++) {
            const int cb_loc = warp_n * 64 + nf * 8 + 2 * (lane & 3);
            const float b0 = sbias[cb_loc], b1 = sbias[cb_loc + 1];
            float e0 = acc[mf][nf][0] + b0, e1 = acc[mf][nf][1] + b1;
            float e2 = acc[mf][nf][2] + b0, e3 = acc[mf][nf][3] + b1;
            if (MODE == 0) {
                const int col = n0 + cb_loc;
                const int sec = col >> 10;
                if (sec == 0) { e0 *= 0.125f; e1 *= 0.125f; e2 *= 0.125f; e3 *= 0.125f; }
                const int c   = col & (CDIM - 1);
                const int h   = c >> 6;
                const int d0  = c & (HD - 1);
                __half* dst = (sec == 0) ? g_q : ((sec == 1) ? g_k : g_v);
                const int bb0 = r0 >> 11, t0 = r0 & (TSEQ - 1);
                const int r1 = r0 + 8;
                const int bb1 = r1 >> 11, t1 = r1 & (TSEQ - 1);
                *(uint32_t*)(dst + (((size_t)bb0 * NH + h) * TSEQ + t0) * HD + d0) = pack_h2(e0, e1);
                *(uint32_t*)(dst + (((size_t)bb1 * NH + h) * TSEQ + t1) * HD + d0) = pack_h2(e2, e3);
            } else {
                *(float2*)(out + (size_t)r0 * CDIM + n0 + cb_loc) = make_float2(e0, e1);
                *(float2*)(out + (size_t)(r0 + 8) * CDIM + n0 + cb_loc) = make_float2(e2, e3);
            }
        }
    }
}

// ---------------------------------------------------------------------------
// Causal flash attention (unchanged from R8): fp16 mma.sync + ldmatrix,
// P in registers. 128 threads (4 warps x 32 rows), K-tile 64, 3-stage KV ring.
// ---------------------------------------------------------------------------
#define QPH 72
#define ATT_Q_BY (128 * QPH * 2)        // 18432
#define ATT_T_BY (64 * QPH * 2)         // 9216 per K or V stage
#define ATT_SMEM (ATT_Q_BY + 6 * ATT_T_BY)   // 73728

__global__ __launch_bounds__(128, 2) void attn_tc_kernel()
{
    extern __shared__ __align__(16) char smc[];
    const uint32_t sb  = smem_u32(smc);
    const uint32_t qb  = sb;
    const uint32_t kb0 = sb + ATT_Q_BY;
    const uint32_t vb0 = kb0 + 3 * ATT_T_BY;

    const int tid  = threadIdx.x;
    const int lane = tid & 31;
    const int w    = tid >> 5;
    const int qi   = (int)(gridDim.x - 1 - blockIdx.x);   // LPT
    const int bh   = blockIdx.y;

    const size_t hoff = (size_t)bh * TSEQ * HD;
    const __half* Qg = g_q + hoff + (size_t)qi * 128 * HD;
    const __half* Kg = g_k + hoff;
    const __half* Vg = g_v + hoff;

    const int nkt = 2 * qi + 2;

#define FKV(slot, kt) do {                                                      \
    const uint32_t kb_ = kb0 + (uint32_t)(slot) * ATT_T_BY;                     \
    const uint32_t vb_ = vb0 + (uint32_t)(slot) * ATT_T_BY;                     \
    const __half* kp = Kg + (size_t)(kt) * 64 * HD;                             \
    const __half* vp = Vg + (size_t)(kt) * 64 * HD;                             \
    _Pragma("unroll")                                                           \
    for (int u = 0; u < 4; u++) {                                               \
        const int idx = tid + u * 128;                                          \
        const int r = idx >> 3, g = idx & 7;                                    \
        cpa16(kb_ + (uint32_t)(r * QPH + g * 8) * 2, kp + (size_t)r * HD + g * 8); \
        cpa16(vb_ + (uint32_t)(r * QPH + g * 8) * 2, vp + (size_t)r * HD + g * 8); \
    }                                                                           \
} while (0)

#pragma unroll
    for (int u = 0; u < 8; u++) {
        const int idx = tid + u * 128;
        const int r = idx >> 3, g = idx & 7;
        cpa16(qb + (uint32_t)(r * QPH + g * 8) * 2, Qg + (size_t)r * HD + g * 8);
    }
    CPA_COMMIT();
    FKV(0, 0); CPA_COMMIT();
    if (nkt > 1) FKV(1, 1);
    CPA_COMMIT();

    cpa_wait<2>();
    __syncthreads();

    const int r8 = lane & 7, q4 = lane >> 3;
    const uint32_t qa_base = (uint32_t)((w * 32 + r8 + (q4 & 1) * 8) * QPH
                                        + (q4 >> 1) * 8) * 2;
    const uint32_t kb_base = (uint32_t)(((q4 >> 1) * 8 + r8) * QPH + (q4 & 1) * 8) * 2;
    const uint32_t vb_base = (uint32_t)(((q4 & 1) * 8 + r8) * QPH + (q4 >> 1) * 8) * 2;

    uint32_t qf[2][4][4];
#pragma unroll
    for (int mf = 0; mf < 2; mf++)
#pragma unroll
        for (int kf = 0; kf < 4; kf++)
            ldsm_x4(qf[mf][kf], qb + qa_base + (uint32_t)(mf * 16 * QPH + kf * 16) * 2);

    float o[2][8][4];
#pragma unroll
    for (int mf = 0; mf < 2; mf++)
#pragma unroll
        for (int nf = 0; nf < 8; nf++)
#pragma unroll
            for (int e = 0; e < 4; e++) o[mf][nf][e] = 0.f;
    float mrow[2][2] = {{-INFINITY, -INFINITY}, {-INFINITY, -INFINITY}};
    float lrow[2][2] = {{0.f, 0.f}, {0.f, 0.f}};

    for (int kt = 0; kt < nkt; kt++) {
        cpa_wait<1>();
        __syncthreads();
        if (kt + 2 < nkt) FKV((kt + 2) % 3, kt + 2);
        CPA_COMMIT();

        const uint32_t kb = kb0 + (uint32_t)(kt % 3) * ATT_T_BY;
        const uint32_t vb = vb0 + (uint32_t)(kt % 3) * ATT_T_BY;

        float s[2][8][4];
#pragma unroll
        for (int mf = 0; mf < 2; mf++)
#pragma unroll
            for (int nf = 0; nf < 8; nf++)
#pragma unroll
                for (int e = 0; e < 4; e++) s[mf][nf][e] = 0.f;

#pragma unroll
        for (int kf = 0; kf < 4; kf++) {
            uint32_t bfr[4][4];
#pragma unroll
            for (int np = 0; np < 4; np++)
                ldsm_x4(bfr[np], kb + kb_base + (uint32_t)(np * 16 * QPH + kf * 16) * 2);
#pragma unroll
            for (int mf = 0; mf < 2; mf++)
#pragma unroll
                for (int nf = 0; nf < 8; nf++)
                    mma_f16(s[mf][nf], qf[mf][kf], &bfr[nf >> 1][(nf & 1) * 2]);
        }

        if (kt >= nkt - 2) {
#pragma unroll
            for (int mf = 0; mf < 2; mf++) {
                const int rb = qi * 128 + w * 32 + mf * 16 + (lane >> 2);
#pragma unroll
                for (int nf = 0; nf < 8; nf++) {
                    const int cg = kt * 64 + nf * 8 + 2 * (lane & 3);
                    if (cg     > rb)     s[mf][nf][0] = -INFINITY;
                    if (cg + 1 > rb)     s[mf][nf][1] = -INFINITY;
                    if (cg     > rb + 8) s[mf][nf][2] = -INFINITY;
                    if (cg + 1 > rb + 8) s[mf][nf][3] = -INFINITY;
                }
            }
        }

        uint32_t pa[2][4][4];
#pragma unroll
        for (int mf = 0; mf < 2; mf++) {
            float rm0 = -INFINITY, rm1 = -INFINITY;
#pragma unroll
            for (int nf = 0; nf < 8; nf++) {
                rm0 = fmaxf(rm0, fmaxf(s[mf][nf][0], s[mf][nf][1]));
                rm1 = fmaxf(rm1, fmaxf(s[mf][nf][2], s[mf][nf][3]));
            }
            rm0 = fmaxf(rm0, __shfl_xor_sync(0xFFFFFFFF, rm0, 1));
            rm0 = fmaxf(rm0, __shfl_xor_sync(0xFFFFFFFF, rm0, 2));
            rm1 = fmaxf(rm1, __shfl_xor_sync(0xFFFFFFFF, rm1, 1));
            rm1 = fmaxf(rm1, __shfl_xor_sync(0xFFFFFFFF, rm1, 2));
            const float mn0 = fmaxf(mrow[mf][0], rm0);
            const float mn1 = fmaxf(mrow[mf][1], rm1);
            const float c0 = __expf(mrow[mf][0] - mn0);
            const float c1 = __expf(mrow[mf][1] - mn1);
            mrow[mf][0] = mn0; mrow[mf][1] = mn1;
            float rs0 = 0.f, rs1 = 0.f;
#pragma unroll
            for (int nf = 0; nf < 8; nf++) {
                const float p0 = __expf(s[mf][nf][0] - mn0);
                const float p1 = __expf(s[mf][nf][1] - mn0);
                const float p2 = __expf(s[mf][nf][2] - mn1);
                const float p3 = __expf(s[mf][nf][3] - mn1);
                rs0 += p0 + p1; rs1 += p2 + p3;
                o[mf][nf][0] *= c0; o[mf][nf][1] *= c0;
                o[mf][nf][2] *= c1; o[mf][nf][3] *= c1;
                s[mf][nf][0] = p0; s[mf][nf][1] = p1;
                s[mf][nf][2] = p2; s[mf][nf][3] = p3;
            }
            rs0 += __shfl_xor_sync(0xFFFFFFFF, rs0, 1);
            rs0 += __shfl_xor_sync(0xFFFFFFFF, rs0, 2);
            rs1 += __shfl_xor_sync(0xFFFFFFFF, rs1, 1);
            rs1 += __shfl_xor_sync(0xFFFFFFFF, rs1, 2);
            lrow[mf][0] = lrow[mf][0] * c0 + rs0;
            lrow[mf][1] = lrow[mf][1] * c1 + rs1;
#pragma unroll
            for (int j = 0; j < 4; j++) {
                pa[mf][j][0] = pack_h2(s[mf][2 * j][0],     s[mf][2 * j][1]);
                pa[mf][j][1] = pack_h2(s[mf][2 * j][2],     s[mf][2 * j][3]);
                pa[mf][j][2] = pack_h2(s[mf][2 * j + 1][0], s[mf][2 * j + 1][1]);
                pa[mf][j][3] = pack_h2(s[mf][2 * j + 1][2], s[mf][2 * j + 1][3]);
            }
        }

#pragma unroll
        for (int kf = 0; kf < 4; kf++) {
            uint32_t vfr[4][4];
#pragma unroll
            for (int dp = 0; dp < 4; dp++)
                ldsm_x4t(vfr[dp], vb + vb_base + (uint32_t)(kf * 16 * QPH + dp * 16) * 2);
#pragma unroll
            for (int mf = 0; mf < 2; mf++)
#pragma unroll
                for (int nf = 0; nf < 8; nf++)
                    mma_f16(o[mf][nf], pa[mf][kf], &vfr[nf >> 1][(nf & 1) * 2]);
        }
    }
#undef FKV

    const int b = bh >> 4;
    const int h = bh & 15;
#pragma unroll
    for (int mf = 0; mf < 2; mf++) {
        const float inv0 = 1.0f / lrow[mf][0];
        const float inv1 = 1.0f / lrow[mf][1];
        const int t0 = qi * 128 + w * 32 + mf * 16 + (lane >> 2);
        __half* y0 = g_y + ((size_t)b * TSEQ + t0) * CDIM + h * 64;
        __half* y1 = g_y + ((size_t)b * TSEQ + t0 + 8) * CDIM + h * 64;
#pragma unroll
        for (int nf = 0; nf < 8; nf++) {
            const int c = nf * 8 + 2 * (lane & 3);
            *(uint32_t*)(y0 + c) = pack_h2(o[mf][nf][0] * inv0, o[mf][nf][1] * inv0);
            *(uint32_t*)(y1 + c) = pack_h2(o[mf][nf][2] * inv1, o[mf][nf][3] * inv1);
        }
    }
}

// ---------------------------------------------------------------------------
extern "C" void kernel_launch(void* const* d_in, const int* in_sizes, int n_in,
                              void* d_out, int out_size)
{
    const float* x      = (const float*)d_in[0];
    const float* W_attn = (const float*)d_in[1];
    const float* b_attn = (const float*)d_in[2];
    const float* W_proj = (const float*)d_in[3];
    const float* b_proj = (const float*)d_in[4];
    float* out = (float*)d_out;

    static bool attr_set = false;
    if (!attr_set) {
        cudaFuncSetAttribute(attn_tc_kernel,
                             cudaFuncAttributeMaxDynamicSharedMemorySize, ATT_SMEM);
        cudaFuncSetAttribute((const void*)tc_gemm_kernel<0>,
                             cudaFuncAttributeMaxDynamicSharedMemorySize, GEMM_DYN);
        cudaFuncSetAttribute((const void*)tc_gemm_kernel<1>,
                             cudaFuncAttributeMaxDynamicSharedMemorySize, GEMM_DYN);
        attr_set = true;
    }

    // 0) fp32 -> fp16 operand prep (single launch)
    to_half_all_kernel<<<(NX8 + NA8 + NP8) / 256, 256>>>(x, W_attn, W_proj);

    // 1) QKV GEMM
    {
        dim3 grid(N3 / BN, MROWS / BM);
        tc_gemm_kernel<0><<<grid, 256, GEMM_DYN>>>(b_attn, nullptr);
    }
    // 2) Flash attention
    {
        dim3 grid(TSEQ / 128, BSZ * NH);
        attn_tc_kernel<<<grid, 128, ATT_SMEM>>>();
    }
    // 3) Projection GEMM
    {
        dim3 grid(CDIM / BN, MROWS / BM);
        tc_gemm_kernel<1><<<grid, 256, GEMM_DYN>>>(b_proj, out);
    }
}